// round 6
// baseline (speedup 1.0000x reference)
#include <cuda_runtime.h>
#include <cuda_bf16.h>
#include <cstdint>

#define DIM 256
#define KSZ 8
#define MAXC 2048
#define CPB 4

__device__ float g_sq[MAXC];
__device__ float g_pc[MAXC];
__device__ float g_an_total;
__device__ __nv_bfloat16 g_hi[MAXC * DIM];
__device__ __nv_bfloat16 g_lo[MAXC * DIM];

__device__ __forceinline__ void cp16(uint32_t smem_addr, const void* gptr) {
    asm volatile("cp.async.cg.shared.global [%0], [%1], 16;\n"
                 :: "r"(smem_addr), "l"(gptr));
}

// ---------------------------------------------------------------------------
// Kernel 1: persistent, 4 classes per block, cp.async double-buffered (r5).
// ---------------------------------------------------------------------------
__global__ void __launch_bounds__(256) centers_kernel(const float* __restrict__ in) {
    int tid  = threadIdx.x;
    int w    = tid >> 5;
    int lane = tid & 31;

    if (blockIdx.x == 0 && tid == 0) g_an_total = 0.f;

    __shared__ __align__(16) float raw[2][KSZ][DIM];
    __shared__ float invn[2][KSZ];
    __shared__ float cen[2][DIM];
    __shared__ float redA[2][KSZ];
    __shared__ float redB[2][KSZ];

    int c0 = blockIdx.x * CPB;

    auto load_class = [&](int c, int buf) {
        const float4* src = (const float4*)(in + (size_t)c * KSZ * DIM);
        float4* dstbase = (float4*)&raw[buf][0][0];
        cp16((uint32_t)__cvta_generic_to_shared(dstbase + tid),       src + tid);
        cp16((uint32_t)__cvta_generic_to_shared(dstbase + tid + 256), src + tid + 256);
        asm volatile("cp.async.commit_group;\n" ::: "memory");
    };

    load_class(c0, 0);

    for (int it = 0; it < CPB; it++) {
        int c   = c0 + it;
        int buf = it & 1;
        if (it + 1 < CPB) {
            load_class(c + 1, buf ^ 1);
            asm volatile("cp.async.wait_group 1;\n" ::: "memory");
        } else {
            asm volatile("cp.async.wait_group 0;\n" ::: "memory");
        }
        __syncthreads();

        float v[8];
        {
            float4 a = *(const float4*)&raw[buf][w][lane * 8];
            float4 b = *(const float4*)&raw[buf][w][lane * 8 + 4];
            v[0]=a.x; v[1]=a.y; v[2]=a.z; v[3]=a.w;
            v[4]=b.x; v[5]=b.y; v[6]=b.z; v[7]=b.w;
        }
        float ss = 0.f;
#pragma unroll
        for (int j = 0; j < 8; j++) ss = fmaf(v[j], v[j], ss);
#pragma unroll
        for (int o = 16; o > 0; o >>= 1) ss += __shfl_xor_sync(0xffffffffu, ss, o);
        if (lane == 0) invn[buf][w] = rsqrtf(ss);
        __syncthreads();

        float cd = 0.f;
#pragma unroll
        for (int k = 0; k < 8; k++) cd = fmaf(raw[buf][k][tid], invn[buf][k], cd);
        cd *= 0.125f;
        cen[buf][tid] = cd;

        __nv_bfloat16 hb = __float2bfloat16(cd);
        g_hi[(size_t)c * DIM + tid] = hb;
        g_lo[(size_t)c * DIM + tid] = __float2bfloat16(cd - __bfloat162float(hb));

        float s2 = cd * cd;
#pragma unroll
        for (int o = 16; o > 0; o >>= 1) s2 += __shfl_xor_sync(0xffffffffu, s2, o);
        if (lane == 0) redA[buf][w] = s2;
        __syncthreads();

        float sqc = 0.f;
#pragma unroll
        for (int k = 0; k < 8; k++) sqc += redA[buf][k];
        if (tid == 0) g_sq[c] = sqc;
        float icn = rsqrtf(sqc);

        float dot = 0.f;
#pragma unroll
        for (int j = 0; j < 8; j++) dot = fmaf(v[j], cen[buf][lane * 8 + j], dot);
#pragma unroll
        for (int o = 16; o > 0; o >>= 1) dot += __shfl_xor_sync(0xffffffffu, dot, o);
        if (lane == 0) {
            float d = invn[buf][w] * icn * dot;
            redB[buf][w] = sqrtf(fmaxf(2.f - 2.f * d, 0.f));
        }
        __syncthreads();
        if (tid == 0) {
            float p = 0.f;
#pragma unroll
            for (int k = 0; k < 8; k++) p += redB[buf][k];
            g_pc[c] = p;
        }
    }
}

// ---------------------------------------------------------------------------
// Kernel 2: 32x64-tile strict-upper-triangle Gram GEMM. 272 blocks, 8 warps
// (2 row x 4 col, warp tile 16x16). B chunks persist (4 bufs, [H|H] reuse);
// A double-buffered (hi then lo). XOR-swizzled smem, pitch 64 bf16.
// ---------------------------------------------------------------------------
__global__ void __launch_bounds__(256) mma_hinge() {
    __shared__ __align__(16) uint8_t sA[2 * 32 * 128];   // 8 KB
    __shared__ __align__(16) uint8_t sB[4 * 64 * 128];   // 32 KB
    __shared__ float sqi_s[32], sqj_s[64];
    __shared__ float warp_sums[8];

    int tid  = threadIdx.x;
    int warp = tid >> 5;
    int lane = tid & 31;

    // blockIdx -> (ri, cj): ri in [0,32), cj in [ri>>1, 16)
    int ri = 0, rem = blockIdx.x;
    while (rem >= 16 - (ri >> 1)) { rem -= 16 - (ri >> 1); ri++; }
    int cj = (ri >> 1) + rem;
    int i0 = ri * 32;
    int j0 = cj * 64;

    int wr = warp >> 2;   // 0..1  (16-row group)
    int wc = warp & 3;    // 0..3  (16-col group)

    uint32_t baseA = (uint32_t)__cvta_generic_to_shared(sA);
    uint32_t baseB = (uint32_t)__cvta_generic_to_shared(sB);

    auto loadA = [&](int it, int buf) {
        const __nv_bfloat16* src = (it < 4) ? g_hi : g_lo;
        int k0 = (it & 3) * 64;
        int r = tid >> 3, q = tid & 7;
        cp16(baseA + buf * 4096 + r * 128 + ((q ^ (r & 7)) << 4),
             src + (size_t)(i0 + r) * DIM + k0 + q * 8);
    };
    auto loadB = [&](int it) {   // it in [0,4)
        int k0 = it * 64;
#pragma unroll
        for (int v = 0; v < 2; v++) {
            int idx = tid + v * 256;
            int r = idx >> 3, q = idx & 7;
            cp16(baseB + it * 8192 + r * 128 + ((q ^ (r & 7)) << 4),
                 g_hi + (size_t)(j0 + r) * DIM + k0 + q * 8);
        }
    };

    loadA(0, 0);
    loadB(0);
    asm volatile("cp.async.commit_group;\n" ::: "memory");

    if (tid < 32)                    sqi_s[tid]      = g_sq[i0 + tid];
    else if (tid >= 64 && tid < 128) sqj_s[tid - 64] = g_sq[j0 + tid - 64];

    float acc[2][4] = {};   // [nj][4]

    for (int it = 0; it < 8; it++) {
        if (it < 7) {
            loadA(it + 1, (it + 1) & 1);
            if (it + 1 < 4) loadB(it + 1);
            asm volatile("cp.async.commit_group;\n" ::: "memory");
            asm volatile("cp.async.wait_group 1;\n" ::: "memory");
        } else {
            asm volatile("cp.async.wait_group 0;\n" ::: "memory");
        }
        __syncthreads();

        uint32_t aoff = baseA + (it & 1) * 4096;
        uint32_t boff = baseB + (it & 3) * 8192;
#pragma unroll
        for (int kk = 0; kk < 64; kk += 16) {
            int cqb = kk >> 3;
            uint32_t afr[4];
            {
                int row = wr * 16 + (lane & 15);
                int cq  = cqb + (lane >> 4);
                uint32_t addr = aoff + row * 128 + ((cq ^ (row & 7)) << 4);
                asm volatile("ldmatrix.sync.aligned.m8n8.x4.shared.b16 {%0,%1,%2,%3}, [%4];"
                    : "=r"(afr[0]), "=r"(afr[1]), "=r"(afr[2]), "=r"(afr[3]) : "r"(addr));
            }
            uint32_t bfr[2][2];
            {
                int row = wc * 16 + ((lane >> 3) & 1) * 8 + (lane & 7);
                int cq  = cqb + (lane >> 4);
                uint32_t addr = boff + row * 128 + ((cq ^ (row & 7)) << 4);
                uint32_t r0, r1, r2, r3;
                asm volatile("ldmatrix.sync.aligned.m8n8.x4.shared.b16 {%0,%1,%2,%3}, [%4];"
                    : "=r"(r0), "=r"(r1), "=r"(r2), "=r"(r3) : "r"(addr));
                bfr[0][0] = r0; bfr[0][1] = r2;
                bfr[1][0] = r1; bfr[1][1] = r3;
            }
#pragma unroll
            for (int nj = 0; nj < 2; nj++) {
                asm volatile(
                    "mma.sync.aligned.m16n8k16.row.col.f32.bf16.bf16.f32 "
                    "{%0,%1,%2,%3}, {%4,%5,%6,%7}, {%8,%9}, {%0,%1,%2,%3};"
                    : "+f"(acc[nj][0]), "+f"(acc[nj][1]),
                      "+f"(acc[nj][2]), "+f"(acc[nj][3])
                    : "r"(afr[0]), "r"(afr[1]), "r"(afr[2]), "r"(afr[3]),
                      "r"(bfr[nj][0]), "r"(bfr[nj][1]));
            }
        }
        __syncthreads();
    }

    // hinge epilogue: strict i<j only (grand total doubled at finalize)
    int qr = lane >> 2;
    int qc = lane & 3;
    float s = 0.f;
#pragma unroll
    for (int h = 0; h < 2; h++) {
        int ii = wr * 16 + h * 8 + qr;
        int i  = i0 + ii;
        float sqi = sqi_s[ii];
#pragma unroll
        for (int nj = 0; nj < 2; nj++)
#pragma unroll
            for (int e = 0; e < 2; e++) {
                int jj = wc * 16 + nj * 8 + qc * 2 + e;
                int j  = j0 + jj;
                float d2 = sqi + sqj_s[jj] - 2.f * acc[nj][h * 2 + e];
                float d  = sqrtf(fmaxf(d2, 1e-12f));
                float hh = fmaxf(0.7f - d, 0.f);
                if (i < j) s += hh;
            }
    }

#pragma unroll
    for (int o = 16; o > 0; o >>= 1) s += __shfl_xor_sync(0xffffffffu, s, o);
    if (lane == 0) warp_sums[warp] = s;
    __syncthreads();
    if (tid == 0) {
        float t = 0.f;
#pragma unroll
        for (int k = 0; k < 8; k++) t += warp_sums[k];
        atomicAdd(&g_an_total, t);
    }
}

// ---------------------------------------------------------------------------
__global__ void __launch_bounds__(256) finalize_kernel(float* __restrict__ out, int n, int C) {
    int tid  = threadIdx.x;
    int w    = tid >> 5;
    int lane = tid & 31;
    __shared__ float sp[8];

    float p = 0.f;
    for (int i = tid; i < C; i += 256) p += g_pc[i];
#pragma unroll
    for (int o = 16; o > 0; o >>= 1) p += __shfl_xor_sync(0xffffffffu, p, o);
    if (lane == 0) sp[w] = p;
    __syncthreads();
    if (tid == 0) {
        float P = 0.f;
#pragma unroll
        for (int k = 0; k < 8; k++) P += sp[k];
        float pc_mean = P / (float)n;
        float an_mean = 2.f * g_an_total / ((float)C * (float)(C - 1));
        out[0] = pc_mean + an_mean;
        out[1] = pc_mean;
        out[2] = an_mean;
    }
}

extern "C" void kernel_launch(void* const* d_in, const int* in_sizes, int n_in,
                              void* d_out, int out_size) {
    const float* in = (const float*)d_in[0];
    int n = in_sizes[0] / DIM;   // 8192
    int C = n / KSZ;             // 1024

    centers_kernel<<<C / CPB, 256>>>(in);
    mma_hinge<<<272, 256>>>();
    finalize_kernel<<<1, 256>>>((float*)d_out, n, C);
}